// round 14
// baseline (speedup 1.0000x reference)
#include <cuda_runtime.h>

#define NN 64
#define MM 8
#define GG 64
#define GH (GG * GG)        /* 4096 */

#define GH_TILE 16
#define N_TILE 8            /* 1 n per thread */
#define NTHREADS 128
#define SB_STRIDE 20        /* floats; 16B-aligned LDS.128 rows */

// ---------------------------------------------------------------------------
__device__ __forceinline__ float det4x4(const float* m) {
    float s0 = m[0]*m[5] - m[1]*m[4];
    float s1 = m[0]*m[6] - m[2]*m[4];
    float s2 = m[0]*m[7] - m[3]*m[4];
    float s3 = m[1]*m[6] - m[2]*m[5];
    float s4 = m[1]*m[7] - m[3]*m[5];
    float s5 = m[2]*m[7] - m[3]*m[6];
    float c5 = m[10]*m[15] - m[11]*m[14];
    float c4 = m[ 9]*m[15] - m[11]*m[13];
    float c3 = m[ 9]*m[14] - m[10]*m[13];
    float c2 = m[ 8]*m[15] - m[11]*m[12];
    float c1 = m[ 8]*m[14] - m[10]*m[12];
    float c0 = m[ 8]*m[13] - m[ 9]*m[12];
    return s0*c5 - s1*c4 + s2*c3 + s3*c2 - s4*c1 + s5*c0;
}

// Adjugate via factored 2x2 minors; returns det.
__device__ __forceinline__ float adj4x4(const float* m, float* b) {
    float s0 = m[0]*m[5] - m[1]*m[4];
    float s1 = m[0]*m[6] - m[2]*m[4];
    float s2 = m[0]*m[7] - m[3]*m[4];
    float s3 = m[1]*m[6] - m[2]*m[5];
    float s4 = m[1]*m[7] - m[3]*m[5];
    float s5 = m[2]*m[7] - m[3]*m[6];
    float c5 = m[10]*m[15] - m[11]*m[14];
    float c4 = m[ 9]*m[15] - m[11]*m[13];
    float c3 = m[ 9]*m[14] - m[10]*m[13];
    float c2 = m[ 8]*m[15] - m[11]*m[12];
    float c1 = m[ 8]*m[14] - m[10]*m[12];
    float c0 = m[ 8]*m[13] - m[ 9]*m[12];
    float det = s0*c5 - s1*c4 + s2*c3 + s3*c2 - s4*c1 + s5*c0;

    b[0]  =  m[5]*c5 - m[6]*c4 + m[7]*c3;
    b[1]  = -m[1]*c5 + m[2]*c4 - m[3]*c3;
    b[2]  =  m[13]*s5 - m[14]*s4 + m[15]*s3;
    b[3]  = -m[ 9]*s5 + m[10]*s4 - m[11]*s3;
    b[4]  = -m[4]*c5 + m[6]*c2 - m[7]*c1;
    b[5]  =  m[0]*c5 - m[2]*c2 + m[3]*c1;
    b[6]  = -m[12]*s5 + m[14]*s2 - m[15]*s1;
    b[7]  =  m[ 8]*s5 - m[10]*s2 + m[11]*s1;
    b[8]  =  m[4]*c4 - m[5]*c2 + m[7]*c0;
    b[9]  = -m[0]*c4 + m[1]*c2 - m[3]*c0;
    b[10] =  m[12]*s4 - m[13]*s2 + m[15]*s0;
    b[11] = -m[ 8]*s4 + m[ 9]*s2 - m[11]*s0;
    b[12] = -m[4]*c3 + m[5]*c1 - m[6]*c0;
    b[13] =  m[0]*c3 - m[1]*c1 + m[2]*c0;
    b[14] = -m[12]*s3 + m[13]*s1 - m[14]*s0;
    b[15] =  m[ 8]*s3 - m[ 9]*s1 + m[10]*s0;
    return det;
}

__device__ __forceinline__ void load16(const float* g, float* r) {
    const float4* p = (const float4*)g;
#pragma unroll
    for (int k = 0; k < 4; k++) {
        float4 v = p[k];
        r[4*k+0] = v.x; r[4*k+1] = v.y; r[4*k+2] = v.z; r[4*k+3] = v.w;
    }
}

struct APack {
    float Cd[4], Co[6], p[4], nca;
};

// Streaming-row apack (low live set).
__device__ __forceinline__ void compute_apack(
    const float* __restrict__ mu_a, const float* __restrict__ sigma_a,
    const float* __restrict__ omega_a, int t, APack& A)
{
    float oa[16], sa[16], adj[16];
    load16(omega_a + (size_t)t * 16, oa);
    load16(sigma_a + (size_t)t * 16, sa);
    float4 mav = ((const float4*)mu_a)[t];
    float ma[4] = {mav.x, mav.y, mav.z, mav.w};

    float detOa = adj4x4(oa, adj);
    float rd = __frcp_rn(detOa);
    float detSa = det4x4(sa);
    A.nca = -__logf(__fdividef(detSa, detOa * detOa));

    float q[4];
#pragma unroll
    for (int i = 0; i < 4; i++) {
        float s = 0.f;
#pragma unroll
        for (int j = 0; j < 4; j++) s = fmaf(adj[4*i+j], ma[j], s);
        q[i] = s;
    }

    float rd2 = rd * rd;
    int oi = 0;
#pragma unroll
    for (int i = 0; i < 4; i++) {
        float Ui[4];
#pragma unroll
        for (int k = 0; k < 4; k++) {
            float s = 0.f;
#pragma unroll
            for (int j = 0; j < 4; j++) s = fmaf(adj[4*i+j], sa[4*j+k], s);
            Ui[k] = s;
        }
        float s = 0.f;
#pragma unroll
        for (int k = 0; k < 4; k++) s = fmaf(Ui[k], adj[4*i+k], s);
        A.Cd[i] = fmaf(q[i], q[i], s) * rd2;
#pragma unroll
        for (int j = 0; j < 4; j++) {
            if (j > i) {
                float s2 = 0.f;
#pragma unroll
                for (int k = 0; k < 4; k++) s2 = fmaf(Ui[k], adj[4*j+k], s2);
                A.Co[oi++] = fmaf(q[i], q[j], s2) * rd2;
            }
        }
    }
#pragma unroll
    for (int i = 0; i < 4; i++) A.p[i] = q[i] * rd;
}

// ---------------------------------------------------------------------------
// Fused kernel, 128 threads/block, grid (256, 8) = 2048 blocks.
// 64-reg cap via (128,8) -> up to 32 resident warps/SM; grid offers 55/SM.
// Phase 1: thread (m = tid>>4, g = tid&15) computes one b-payload into smem.
// Phase 2: thread owns (n0 + (tid>>4), gh0 + (tid&15)); 8-m loop with
//          split accumulators + sigmoid.
// ---------------------------------------------------------------------------
__global__ void __launch_bounds__(NTHREADS, 8) species_fused_kernel(
    const float* __restrict__ mu_a, const float* __restrict__ sigma_a,
    const float* __restrict__ omega_a, const float* __restrict__ mu_b,
    const float* __restrict__ sigma_b, const float* __restrict__ omega_b,
    const float* __restrict__ chi, float* __restrict__ out)
{
    __shared__ float sbuf[MM * GH_TILE * SB_STRIDE];   // 10 KB

    int tid = threadIdx.x;
    int gh0 = blockIdx.x * GH_TILE;
    int n0  = blockIdx.y * N_TILE;

    // ---- phase 1: per-b payload into smem (streaming T-columns) ----
    {
        int m = tid >> 4;
        int g = tid & 15;
        int bi = m * GH + gh0 + g;

        float sb[16], adjS[16], ob[16];
        load16(sigma_b + (size_t)bi * 16, sb);
        load16(omega_b + (size_t)bi * 16, ob);
        float4 mbv = ((const float4*)mu_b)[bi];
        float mb[4] = {mbv.x, mbv.y, mbv.z, mbv.w};

        float detSb = adj4x4(sb, adjS);
        float rs = __frcp_rn(detSb);
        float detOb = det4x4(ob);
        float cb = __logf(__fdividef(detSb, detOb * detOb));

        // E = Ob^T * (adjS * Ob), streamed column-by-column of T = adjS*Ob.
        // Upper-tri order: (0,1)=0 (0,2)=1 (0,3)=2 (1,2)=3 (1,3)=4 (2,3)=5
        float Ed[4], Eo[6];
        float rs2 = 2.0f * rs;
#pragma unroll
        for (int c = 0; c < 4; c++) {
            float Tc[4];
#pragma unroll
            for (int k = 0; k < 4; k++) {
                float s = 0.f;
#pragma unroll
                for (int j = 0; j < 4; j++) s = fmaf(adjS[4*k+j], ob[4*j+c], s);
                Tc[k] = s;
            }
#pragma unroll
            for (int r = 0; r < 4; r++) {
                if (r < c) {
                    float s = 0.f;
#pragma unroll
                    for (int k = 0; k < 4; k++) s = fmaf(ob[4*k+r], Tc[k], s);
                    int idx = (r == 0) ? (c - 1) : ((r == 1) ? (c + 1) : 5);
                    Eo[idx] = s * rs2;
                } else if (r == c) {
                    float s = 0.f;
#pragma unroll
                    for (int k = 0; k < 4; k++) s = fmaf(ob[4*k+r], Tc[k], s);
                    Ed[c] = s * rs;
                }
            }
        }

        // v = adjS mb; f' = -2 rs Ob^T v; h = rs (mb.v)
        float v[4], fp[4];
        float h = 0.f;
#pragma unroll
        for (int r = 0; r < 4; r++) {
            float s = 0.f;
#pragma unroll
            for (int k = 0; k < 4; k++) s = fmaf(adjS[4*r+k], mb[k], s);
            v[r] = s;
            h = fmaf(mb[r], s, h);
        }
        float nrs2 = -2.0f * rs;
#pragma unroll
        for (int r = 0; r < 4; r++) {
            float s = 0.f;
#pragma unroll
            for (int k = 0; k < 4; k++) s = fmaf(ob[4*k+r], v[k], s);
            fp[r] = s * nrs2;
        }
        float hcb = fmaf(h, rs, cb - 4.0f);

        float4* d = (float4*)&sbuf[(m * GH_TILE + g) * SB_STRIDE];
        d[0] = make_float4(Ed[0], Ed[1], Ed[2], Ed[3]);
        d[1] = make_float4(Eo[0], Eo[1], Eo[2], Eo[3]);
        d[2] = make_float4(Eo[4], Eo[5], fp[0], fp[1]);
        d[3] = make_float4(fp[2], fp[3], hcb, 0.f);
    }
    __syncthreads();

    // ---- phase 2: one n per thread ----
    int lg = tid & 15;
    int wn = tid >> 4;          // 0..7
    int gh = gh0 + lg;
    int n  = n0 + wn;
    int t  = n * GH + gh;

    APack A;
    compute_apack(mu_a, sigma_a, omega_a, t, A);
    float chiv = chi[t];

    float* outp = out + (size_t)n * (MM * GH) + gh;
    const float* sbb = &sbuf[lg * SB_STRIDE];

#pragma unroll
    for (int m = 0; m < MM; m++) {
        const float4* s4 = (const float4*)(sbb + m * (GH_TILE * SB_STRIDE));
        float4 e0 = s4[0];
        float4 e1 = s4[1];
        float4 e2 = s4[2];
        float4 e3 = s4[3];

        // split accumulators to halve the dependency chain
        float Xa = e3.z + A.nca;
        float Xb = 0.f;
        Xa = fmaf(e0.x, A.Cd[0], Xa);
        Xb = fmaf(e0.y, A.Cd[1], Xb);
        Xa = fmaf(e0.z, A.Cd[2], Xa);
        Xb = fmaf(e0.w, A.Cd[3], Xb);
        Xa = fmaf(e1.x, A.Co[0], Xa);
        Xb = fmaf(e1.y, A.Co[1], Xb);
        Xa = fmaf(e1.z, A.Co[2], Xa);
        Xb = fmaf(e1.w, A.Co[3], Xb);
        Xa = fmaf(e2.x, A.Co[4], Xa);
        Xb = fmaf(e2.y, A.Co[5], Xb);
        Xa = fmaf(e2.z, A.p[0], Xa);
        Xb = fmaf(e2.w, A.p[1], Xb);
        Xa = fmaf(e3.x, A.p[2], Xa);
        Xb = fmaf(e3.y, A.p[3], Xb);

        float X = Xa + Xb;
        float g = __expf(0.1f * X);
        float S = __fdividef(chiv, 1.0f + g);
        outp[(size_t)m * GH] = S;
    }
}

// ---------------------------------------------------------------------------
extern "C" void kernel_launch(void* const* d_in, const int* in_sizes, int n_in,
                              void* d_out, int out_size)
{
    const float* mu_a    = (const float*)d_in[0];
    const float* sigma_a = (const float*)d_in[1];
    const float* omega_a = (const float*)d_in[2];
    const float* mu_b    = (const float*)d_in[3];
    const float* sigma_b = (const float*)d_in[4];
    const float* omega_b = (const float*)d_in[5];
    const float* chi     = (const float*)d_in[6];
    float* out = (float*)d_out;

    dim3 grid(GH / GH_TILE, NN / N_TILE);   // (256, 8) = 2048 blocks
    species_fused_kernel<<<grid, NTHREADS>>>(mu_a, sigma_a, omega_a,
                                             mu_b, sigma_b, omega_b, chi, out);
}

// round 15
// speedup vs baseline: 1.2569x; 1.2569x over previous
#include <cuda_runtime.h>
#include <cstdint>

#define NN 64
#define MM 8
#define GG 64
#define GH (GG * GG)        /* 4096 */

#define GH_TILE 16
#define N_TILE 16           /* 2 n per thread, 8 n-slots */
#define NTHREADS 128
#define SB_STRIDE 20        /* floats; 16B-aligned LDS.128 rows */
#define PRE_STRIDE 36       /* staged A1 entry: sigma(16) omega(16) pad(4) */

// smem: sbuf (bpack) 8*16*20 = 2560 floats | sPre 128*36 = 4608 floats
#define SMEM_FLOATS (MM * GH_TILE * SB_STRIDE + NTHREADS * PRE_STRIDE)  /* 7168 = 28 KB */

#define CP_ASYNC16(dst_u32, src_ptr) \
    asm volatile("cp.async.cg.shared.global [%0], [%1], 16;" \
                 :: "r"(dst_u32), "l"(src_ptr) : "memory")
#define CP_COMMIT() asm volatile("cp.async.commit_group;" ::: "memory")
#define CP_WAIT0()  asm volatile("cp.async.wait_group 0;" ::: "memory")

// ---------------------------------------------------------------------------
__device__ __forceinline__ float det4x4(const float* m) {
    float s0 = m[0]*m[5] - m[1]*m[4];
    float s1 = m[0]*m[6] - m[2]*m[4];
    float s2 = m[0]*m[7] - m[3]*m[4];
    float s3 = m[1]*m[6] - m[2]*m[5];
    float s4 = m[1]*m[7] - m[3]*m[5];
    float s5 = m[2]*m[7] - m[3]*m[6];
    float c5 = m[10]*m[15] - m[11]*m[14];
    float c4 = m[ 9]*m[15] - m[11]*m[13];
    float c3 = m[ 9]*m[14] - m[10]*m[13];
    float c2 = m[ 8]*m[15] - m[11]*m[12];
    float c1 = m[ 8]*m[14] - m[10]*m[12];
    float c0 = m[ 8]*m[13] - m[ 9]*m[12];
    return s0*c5 - s1*c4 + s2*c3 + s3*c2 - s4*c1 + s5*c0;
}

// Adjugate via factored 2x2 minors; returns det.
__device__ __forceinline__ float adj4x4(const float* m, float* b) {
    float s0 = m[0]*m[5] - m[1]*m[4];
    float s1 = m[0]*m[6] - m[2]*m[4];
    float s2 = m[0]*m[7] - m[3]*m[4];
    float s3 = m[1]*m[6] - m[2]*m[5];
    float s4 = m[1]*m[7] - m[3]*m[5];
    float s5 = m[2]*m[7] - m[3]*m[6];
    float c5 = m[10]*m[15] - m[11]*m[14];
    float c4 = m[ 9]*m[15] - m[11]*m[13];
    float c3 = m[ 9]*m[14] - m[10]*m[13];
    float c2 = m[ 8]*m[15] - m[11]*m[12];
    float c1 = m[ 8]*m[14] - m[10]*m[12];
    float c0 = m[ 8]*m[13] - m[ 9]*m[12];
    float det = s0*c5 - s1*c4 + s2*c3 + s3*c2 - s4*c1 + s5*c0;

    b[0]  =  m[5]*c5 - m[6]*c4 + m[7]*c3;
    b[1]  = -m[1]*c5 + m[2]*c4 - m[3]*c3;
    b[2]  =  m[13]*s5 - m[14]*s4 + m[15]*s3;
    b[3]  = -m[ 9]*s5 + m[10]*s4 - m[11]*s3;
    b[4]  = -m[4]*c5 + m[6]*c2 - m[7]*c1;
    b[5]  =  m[0]*c5 - m[2]*c2 + m[3]*c1;
    b[6]  = -m[12]*s5 + m[14]*s2 - m[15]*s1;
    b[7]  =  m[ 8]*s5 - m[10]*s2 + m[11]*s1;
    b[8]  =  m[4]*c4 - m[5]*c2 + m[7]*c0;
    b[9]  = -m[0]*c4 + m[1]*c2 - m[3]*c0;
    b[10] =  m[12]*s4 - m[13]*s2 + m[15]*s0;
    b[11] = -m[ 8]*s4 + m[ 9]*s2 - m[11]*s0;
    b[12] = -m[4]*c3 + m[5]*c1 - m[6]*c0;
    b[13] =  m[0]*c3 - m[1]*c1 + m[2]*c0;
    b[14] = -m[12]*s3 + m[13]*s1 - m[14]*s0;
    b[15] =  m[ 8]*s3 - m[ 9]*s1 + m[10]*s0;
    return det;
}

__device__ __forceinline__ void load16(const float* g, float* r) {
    const float4* p = (const float4*)g;
#pragma unroll
    for (int k = 0; k < 4; k++) {
        float4 v = p[k];
        r[4*k+0] = v.x; r[4*k+1] = v.y; r[4*k+2] = v.z; r[4*k+3] = v.w;
    }
}

struct APack {
    float Cd[4], Co[6], p[4], nca;
};

// Streaming-row apack core (sa/oa already in registers).
__device__ __forceinline__ void apack_core(
    const float* oa, const float* sa, float4 mav, APack& A)
{
    float ma[4] = {mav.x, mav.y, mav.z, mav.w};
    float adj[16];
    float detOa = adj4x4(oa, adj);
    float rd = __frcp_rn(detOa);
    float detSa = det4x4(sa);
    A.nca = -__logf(__fdividef(detSa, detOa * detOa));

    float q[4];
#pragma unroll
    for (int i = 0; i < 4; i++) {
        float s = 0.f;
#pragma unroll
        for (int j = 0; j < 4; j++) s = fmaf(adj[4*i+j], ma[j], s);
        q[i] = s;
    }

    float rd2 = rd * rd;
    int oi = 0;
#pragma unroll
    for (int i = 0; i < 4; i++) {
        float Ui[4];
#pragma unroll
        for (int k = 0; k < 4; k++) {
            float s = 0.f;
#pragma unroll
            for (int j = 0; j < 4; j++) s = fmaf(adj[4*i+j], sa[4*j+k], s);
            Ui[k] = s;
        }
        float s = 0.f;
#pragma unroll
        for (int k = 0; k < 4; k++) s = fmaf(Ui[k], adj[4*i+k], s);
        A.Cd[i] = fmaf(q[i], q[i], s) * rd2;
#pragma unroll
        for (int j = 0; j < 4; j++) {
            if (j > i) {
                float s2 = 0.f;
#pragma unroll
                for (int k = 0; k < 4; k++) s2 = fmaf(Ui[k], adj[4*j+k], s2);
                A.Co[oi++] = fmaf(q[i], q[j], s2) * rd2;
            }
        }
    }
#pragma unroll
    for (int i = 0; i < 4; i++) A.p[i] = q[i] * rd;
}

// ---------------------------------------------------------------------------
// Fused kernel, 128 threads/block, grid (256, 4). 72-reg cap via (128,7).
// Phase 0: cp.async prefetch of A1 inputs (sigma_a, omega_a) into sPre.
// Phase 1: per-thread b-payload -> sbuf (hides the prefetch).
// Phase 2: A1 from smem, A2 via LDG (overlaps A1 compute); 8-m loop.
// ---------------------------------------------------------------------------
__global__ void __launch_bounds__(NTHREADS, 7) species_fused_kernel(
    const float* __restrict__ mu_a, const float* __restrict__ sigma_a,
    const float* __restrict__ omega_a, const float* __restrict__ mu_b,
    const float* __restrict__ sigma_b, const float* __restrict__ omega_b,
    const float* __restrict__ chi, float* __restrict__ out)
{
    extern __shared__ __align__(16) float smem[];
    float* sbuf = smem;                                    // 2560 floats
    float* sPre = smem + MM * GH_TILE * SB_STRIDE;         // 4608 floats

    int tid = threadIdx.x;
    int gh0 = blockIdx.x * GH_TILE;
    int n0  = blockIdx.y * N_TILE;

    // ---- phase 0: cp.async prefetch A1 inputs ----
    // entry e (= tid ordering): lg = e&15, wn = e>>4; t1 = (n0+wn)*GH + gh0+lg
    {
        unsigned int sPre_u = (unsigned int)__cvta_generic_to_shared(sPre);
#pragma unroll
        for (int it = 0; it < 4; it++) {          // sigma_a: 512 16B chunks
            int c = tid + it * NTHREADS;
            int e = c >> 2, sub = c & 3;
            int t = (n0 + (e >> 4)) * GH + gh0 + (e & 15);
            CP_ASYNC16(sPre_u + (e * PRE_STRIDE + sub * 4) * 4,
                       sigma_a + (size_t)t * 16 + sub * 4);
        }
#pragma unroll
        for (int it = 0; it < 4; it++) {          // omega_a
            int c = tid + it * NTHREADS;
            int e = c >> 2, sub = c & 3;
            int t = (n0 + (e >> 4)) * GH + gh0 + (e & 15);
            CP_ASYNC16(sPre_u + (e * PRE_STRIDE + 16 + sub * 4) * 4,
                       omega_a + (size_t)t * 16 + sub * 4);
        }
        CP_COMMIT();
    }

    // ---- phase 1: per-b payload into sbuf (streaming T-columns) ----
    {
        int m = tid >> 4;
        int g = tid & 15;
        int bi = m * GH + gh0 + g;

        float sb[16], adjS[16], ob[16];
        load16(sigma_b + (size_t)bi * 16, sb);
        load16(omega_b + (size_t)bi * 16, ob);
        float4 mbv = ((const float4*)mu_b)[bi];
        float mb[4] = {mbv.x, mbv.y, mbv.z, mbv.w};

        float detSb = adj4x4(sb, adjS);
        float rs = __frcp_rn(detSb);
        float detOb = det4x4(ob);
        float cb = __logf(__fdividef(detSb, detOb * detOb));

        // E = Ob^T * (adjS * Ob), streamed columns of T = adjS*Ob.
        // Upper-tri order: (0,1)=0 (0,2)=1 (0,3)=2 (1,2)=3 (1,3)=4 (2,3)=5
        float Ed[4], Eo[6];
        float rs2 = 2.0f * rs;
#pragma unroll
        for (int c = 0; c < 4; c++) {
            float Tc[4];
#pragma unroll
            for (int k = 0; k < 4; k++) {
                float s = 0.f;
#pragma unroll
                for (int j = 0; j < 4; j++) s = fmaf(adjS[4*k+j], ob[4*j+c], s);
                Tc[k] = s;
            }
#pragma unroll
            for (int r = 0; r < 4; r++) {
                if (r < c) {
                    float s = 0.f;
#pragma unroll
                    for (int k = 0; k < 4; k++) s = fmaf(ob[4*k+r], Tc[k], s);
                    int idx = (r == 0) ? (c - 1) : ((r == 1) ? (c + 1) : 5);
                    Eo[idx] = s * rs2;
                } else if (r == c) {
                    float s = 0.f;
#pragma unroll
                    for (int k = 0; k < 4; k++) s = fmaf(ob[4*k+r], Tc[k], s);
                    Ed[c] = s * rs;
                }
            }
        }

        // v = adjS mb; f' = -2 rs Ob^T v; h = rs (mb.v)
        float v[4], fp[4];
        float h = 0.f;
#pragma unroll
        for (int r = 0; r < 4; r++) {
            float s = 0.f;
#pragma unroll
            for (int k = 0; k < 4; k++) s = fmaf(adjS[4*r+k], mb[k], s);
            v[r] = s;
            h = fmaf(mb[r], s, h);
        }
        float nrs2 = -2.0f * rs;
#pragma unroll
        for (int r = 0; r < 4; r++) {
            float s = 0.f;
#pragma unroll
            for (int k = 0; k < 4; k++) s = fmaf(ob[4*k+r], v[k], s);
            fp[r] = s * nrs2;
        }
        float hcb = fmaf(h, rs, cb - 4.0f);

        float4* d = (float4*)&sbuf[(m * GH_TILE + g) * SB_STRIDE];
        d[0] = make_float4(Ed[0], Ed[1], Ed[2], Ed[3]);
        d[1] = make_float4(Eo[0], Eo[1], Eo[2], Eo[3]);
        d[2] = make_float4(Eo[4], Eo[5], fp[0], fp[1]);
        d[3] = make_float4(fp[2], fp[3], hcb, 0.f);
    }
    CP_WAIT0();
    __syncthreads();

    // ---- phase 2: two n per thread ----
    int lg = tid & 15;
    int wn = tid >> 4;          // 0..7
    int gh = gh0 + lg;
    int n1 = n0 + wn;
    int n2 = n1 + 8;
    int t1 = n1 * GH + gh;
    int t2 = n2 * GH + gh;

    // A1 from prefetched smem
    APack A1;
    {
        const float* ent = sPre + tid * PRE_STRIDE;
        float sa[16], oa[16];
        load16(ent, sa);
        load16(ent + 16, oa);
        float4 mav1 = ((const float4*)mu_a)[t1];
        apack_core(oa, sa, mav1, A1);
    }
    // A2 via LDG (hoisted loads overlap A1 compute)
    APack A2;
    {
        float sa[16], oa[16];
        load16(sigma_a + (size_t)t2 * 16, sa);
        load16(omega_a + (size_t)t2 * 16, oa);
        float4 mav2 = ((const float4*)mu_a)[t2];
        apack_core(oa, sa, mav2, A2);
    }
    float chi1 = chi[t1];
    float chi2 = chi[t2];

    float* out1 = out + (size_t)n1 * (MM * GH) + gh;
    float* out2 = out + (size_t)n2 * (MM * GH) + gh;
    const float* sbb = &sbuf[lg * SB_STRIDE];

#pragma unroll
    for (int m = 0; m < MM; m++) {
        const float4* s4 = (const float4*)(sbb + m * (GH_TILE * SB_STRIDE));
        float4 e0 = s4[0];
        float4 e1 = s4[1];
        float4 e2 = s4[2];
        float4 e3 = s4[3];

        float Xa1 = e3.z + A1.nca;
        float Xb1 = 0.f;
        float Xa2 = e3.z + A2.nca;
        float Xb2 = 0.f;
        Xa1 = fmaf(e0.x, A1.Cd[0], Xa1);  Xa2 = fmaf(e0.x, A2.Cd[0], Xa2);
        Xb1 = fmaf(e0.y, A1.Cd[1], Xb1);  Xb2 = fmaf(e0.y, A2.Cd[1], Xb2);
        Xa1 = fmaf(e0.z, A1.Cd[2], Xa1);  Xa2 = fmaf(e0.z, A2.Cd[2], Xa2);
        Xb1 = fmaf(e0.w, A1.Cd[3], Xb1);  Xb2 = fmaf(e0.w, A2.Cd[3], Xb2);
        Xa1 = fmaf(e1.x, A1.Co[0], Xa1);  Xa2 = fmaf(e1.x, A2.Co[0], Xa2);
        Xb1 = fmaf(e1.y, A1.Co[1], Xb1);  Xb2 = fmaf(e1.y, A2.Co[1], Xb2);
        Xa1 = fmaf(e1.z, A1.Co[2], Xa1);  Xa2 = fmaf(e1.z, A2.Co[2], Xa2);
        Xb1 = fmaf(e1.w, A1.Co[3], Xb1);  Xb2 = fmaf(e1.w, A2.Co[3], Xb2);
        Xa1 = fmaf(e2.x, A1.Co[4], Xa1);  Xa2 = fmaf(e2.x, A2.Co[4], Xa2);
        Xb1 = fmaf(e2.y, A1.Co[5], Xb1);  Xb2 = fmaf(e2.y, A2.Co[5], Xb2);
        Xa1 = fmaf(e2.z, A1.p[0], Xa1);   Xa2 = fmaf(e2.z, A2.p[0], Xa2);
        Xb1 = fmaf(e2.w, A1.p[1], Xb1);   Xb2 = fmaf(e2.w, A2.p[1], Xb2);
        Xa1 = fmaf(e3.x, A1.p[2], Xa1);   Xa2 = fmaf(e3.x, A2.p[2], Xa2);
        Xb1 = fmaf(e3.y, A1.p[3], Xb1);   Xb2 = fmaf(e3.y, A2.p[3], Xb2);

        float X1 = Xa1 + Xb1;
        float X2 = Xa2 + Xb2;

        float g1 = __expf(0.1f * X1);
        float g2 = __expf(0.1f * X2);
        float S1 = __fdividef(chi1, 1.0f + g1);
        float S2 = __fdividef(chi2, 1.0f + g2);
        out1[(size_t)m * GH] = S1;
        out2[(size_t)m * GH] = S2;
    }
}

// ---------------------------------------------------------------------------
extern "C" void kernel_launch(void* const* d_in, const int* in_sizes, int n_in,
                              void* d_out, int out_size)
{
    const float* mu_a    = (const float*)d_in[0];
    const float* sigma_a = (const float*)d_in[1];
    const float* omega_a = (const float*)d_in[2];
    const float* mu_b    = (const float*)d_in[3];
    const float* sigma_b = (const float*)d_in[4];
    const float* omega_b = (const float*)d_in[5];
    const float* chi     = (const float*)d_in[6];
    float* out = (float*)d_out;

    const int smem_bytes = SMEM_FLOATS * 4;   // 28672
    static int attr_set = 0;
    if (!attr_set) {
        cudaFuncSetAttribute(species_fused_kernel,
                             cudaFuncAttributeMaxDynamicSharedMemorySize,
                             smem_bytes);
        attr_set = 1;
    }

    dim3 grid(GH / GH_TILE, NN / N_TILE);   // (256, 4) = 1024 blocks
    species_fused_kernel<<<grid, NTHREADS, smem_bytes>>>(
        mu_a, sigma_a, omega_a, mu_b, sigma_b, omega_b, chi, out);
}

// round 16
// speedup vs baseline: 1.3156x; 1.0467x over previous
#include <cuda_runtime.h>

#define NN 64
#define MM 8
#define GG 64
#define GH (GG * GG)        /* 4096 */

#define GH_TILE 16
#define N_TILE 16           /* 2 n per thread, 8 n-slots */
#define NTHREADS 128
#define SB_STRIDE 20        /* floats; 16B-aligned LDS.128 rows */

// ---------------------------------------------------------------------------
__device__ __forceinline__ float det4x4(const float* m) {
    float s0 = m[0]*m[5] - m[1]*m[4];
    float s1 = m[0]*m[6] - m[2]*m[4];
    float s2 = m[0]*m[7] - m[3]*m[4];
    float s3 = m[1]*m[6] - m[2]*m[5];
    float s4 = m[1]*m[7] - m[3]*m[5];
    float s5 = m[2]*m[7] - m[3]*m[6];
    float c5 = m[10]*m[15] - m[11]*m[14];
    float c4 = m[ 9]*m[15] - m[11]*m[13];
    float c3 = m[ 9]*m[14] - m[10]*m[13];
    float c2 = m[ 8]*m[15] - m[11]*m[12];
    float c1 = m[ 8]*m[14] - m[10]*m[12];
    float c0 = m[ 8]*m[13] - m[ 9]*m[12];
    return s0*c5 - s1*c4 + s2*c3 + s3*c2 - s4*c1 + s5*c0;
}

// Adjugate via factored 2x2 minors; returns det.
__device__ __forceinline__ float adj4x4(const float* m, float* b) {
    float s0 = m[0]*m[5] - m[1]*m[4];
    float s1 = m[0]*m[6] - m[2]*m[4];
    float s2 = m[0]*m[7] - m[3]*m[4];
    float s3 = m[1]*m[6] - m[2]*m[5];
    float s4 = m[1]*m[7] - m[3]*m[5];
    float s5 = m[2]*m[7] - m[3]*m[6];
    float c5 = m[10]*m[15] - m[11]*m[14];
    float c4 = m[ 9]*m[15] - m[11]*m[13];
    float c3 = m[ 9]*m[14] - m[10]*m[13];
    float c2 = m[ 8]*m[15] - m[11]*m[12];
    float c1 = m[ 8]*m[14] - m[10]*m[12];
    float c0 = m[ 8]*m[13] - m[ 9]*m[12];
    float det = s0*c5 - s1*c4 + s2*c3 + s3*c2 - s4*c1 + s5*c0;

    b[0]  =  m[5]*c5 - m[6]*c4 + m[7]*c3;
    b[1]  = -m[1]*c5 + m[2]*c4 - m[3]*c3;
    b[2]  =  m[13]*s5 - m[14]*s4 + m[15]*s3;
    b[3]  = -m[ 9]*s5 + m[10]*s4 - m[11]*s3;
    b[4]  = -m[4]*c5 + m[6]*c2 - m[7]*c1;
    b[5]  =  m[0]*c5 - m[2]*c2 + m[3]*c1;
    b[6]  = -m[12]*s5 + m[14]*s2 - m[15]*s1;
    b[7]  =  m[ 8]*s5 - m[10]*s2 + m[11]*s1;
    b[8]  =  m[4]*c4 - m[5]*c2 + m[7]*c0;
    b[9]  = -m[0]*c4 + m[1]*c2 - m[3]*c0;
    b[10] =  m[12]*s4 - m[13]*s2 + m[15]*s0;
    b[11] = -m[ 8]*s4 + m[ 9]*s2 - m[11]*s0;
    b[12] = -m[4]*c3 + m[5]*c1 - m[6]*c0;
    b[13] =  m[0]*c3 - m[1]*c1 + m[2]*c0;
    b[14] = -m[12]*s3 + m[13]*s1 - m[14]*s0;
    b[15] =  m[ 8]*s3 - m[ 9]*s1 + m[10]*s0;
    return det;
}

__device__ __forceinline__ void load16(const float* g, float* r) {
    const float4* p = (const float4*)g;
#pragma unroll
    for (int k = 0; k < 4; k++) {
        float4 v = p[k];
        r[4*k+0] = v.x; r[4*k+1] = v.y; r[4*k+2] = v.z; r[4*k+3] = v.w;
    }
}

struct APack {
    float Cd[4], Co[6], p[4], nca;
};

// Streaming-row apack (low live set).
__device__ __forceinline__ void compute_apack(
    const float* __restrict__ mu_a, const float* __restrict__ sigma_a,
    const float* __restrict__ omega_a, int t, APack& A)
{
    float oa[16], sa[16], adj[16];
    load16(omega_a + (size_t)t * 16, oa);
    load16(sigma_a + (size_t)t * 16, sa);
    float4 mav = ((const float4*)mu_a)[t];
    float ma[4] = {mav.x, mav.y, mav.z, mav.w};

    float detOa = adj4x4(oa, adj);
    float rd = __frcp_rn(detOa);
    float detSa = det4x4(sa);
    A.nca = -__logf(__fdividef(detSa, detOa * detOa));

    float q[4];
#pragma unroll
    for (int i = 0; i < 4; i++) {
        float s = 0.f;
#pragma unroll
        for (int j = 0; j < 4; j++) s = fmaf(adj[4*i+j], ma[j], s);
        q[i] = s;
    }

    float rd2 = rd * rd;
    int oi = 0;
#pragma unroll
    for (int i = 0; i < 4; i++) {
        float Ui[4];
#pragma unroll
        for (int k = 0; k < 4; k++) {
            float s = 0.f;
#pragma unroll
            for (int j = 0; j < 4; j++) s = fmaf(adj[4*i+j], sa[4*j+k], s);
            Ui[k] = s;
        }
        float s = 0.f;
#pragma unroll
        for (int k = 0; k < 4; k++) s = fmaf(Ui[k], adj[4*i+k], s);
        A.Cd[i] = fmaf(q[i], q[i], s) * rd2;
#pragma unroll
        for (int j = 0; j < 4; j++) {
            if (j > i) {
                float s2 = 0.f;
#pragma unroll
                for (int k = 0; k < 4; k++) s2 = fmaf(Ui[k], adj[4*j+k], s2);
                A.Co[oi++] = fmaf(q[i], q[j], s2) * rd2;
            }
        }
    }
#pragma unroll
    for (int i = 0; i < 4; i++) A.p[i] = q[i] * rd;
}

__device__ __forceinline__ float fast_tanh(float x) {
    float r;
    asm("tanh.approx.f32 %0, %1;" : "=f"(r) : "f"(x));
    return r;
}

// ---------------------------------------------------------------------------
// Fused kernel, 128 threads/block, grid (256, 4). 72-reg cap via (128,7).
// Phase 1: thread (m = tid>>4, g = tid&15) computes one b-payload into smem.
// Phase 2: thread owns (n0+wn, gh) and (n0+wn+8, gh); 8-m loop with
//          split accumulators + tanh-based sigmoid.
// ---------------------------------------------------------------------------
__global__ void __launch_bounds__(NTHREADS, 7) species_fused_kernel(
    const float* __restrict__ mu_a, const float* __restrict__ sigma_a,
    const float* __restrict__ omega_a, const float* __restrict__ mu_b,
    const float* __restrict__ sigma_b, const float* __restrict__ omega_b,
    const float* __restrict__ chi, float* __restrict__ out)
{
    __shared__ float sbuf[MM * GH_TILE * SB_STRIDE];   // 10 KB

    int tid = threadIdx.x;
    int gh0 = blockIdx.x * GH_TILE;
    int n0  = blockIdx.y * N_TILE;

    // ---- phase 1: per-b payload into smem (streaming T-columns) ----
    {
        int m = tid >> 4;
        int g = tid & 15;
        int bi = m * GH + gh0 + g;

        float sb[16], adjS[16], ob[16];
        load16(sigma_b + (size_t)bi * 16, sb);
        load16(omega_b + (size_t)bi * 16, ob);
        float4 mbv = ((const float4*)mu_b)[bi];
        float mb[4] = {mbv.x, mbv.y, mbv.z, mbv.w};

        float detSb = adj4x4(sb, adjS);
        float rs = __frcp_rn(detSb);
        float detOb = det4x4(ob);
        float cb = __logf(__fdividef(detSb, detOb * detOb));

        // E = Ob^T * (adjS * Ob), streamed column-by-column of T = adjS*Ob.
        // Upper-tri order: (0,1)=0 (0,2)=1 (0,3)=2 (1,2)=3 (1,3)=4 (2,3)=5
        float Ed[4], Eo[6];
        float rs2 = 2.0f * rs;
#pragma unroll
        for (int c = 0; c < 4; c++) {
            float Tc[4];
#pragma unroll
            for (int k = 0; k < 4; k++) {
                float s = 0.f;
#pragma unroll
                for (int j = 0; j < 4; j++) s = fmaf(adjS[4*k+j], ob[4*j+c], s);
                Tc[k] = s;
            }
#pragma unroll
            for (int r = 0; r < 4; r++) {
                if (r < c) {
                    float s = 0.f;
#pragma unroll
                    for (int k = 0; k < 4; k++) s = fmaf(ob[4*k+r], Tc[k], s);
                    int idx = (r == 0) ? (c - 1) : ((r == 1) ? (c + 1) : 5);
                    Eo[idx] = s * rs2;
                } else if (r == c) {
                    float s = 0.f;
#pragma unroll
                    for (int k = 0; k < 4; k++) s = fmaf(ob[4*k+r], Tc[k], s);
                    Ed[c] = s * rs;
                }
            }
        }

        // v = adjS mb; f' = -2 rs Ob^T v; h = rs (mb.v)
        float v[4], fp[4];
        float h = 0.f;
#pragma unroll
        for (int r = 0; r < 4; r++) {
            float s = 0.f;
#pragma unroll
            for (int k = 0; k < 4; k++) s = fmaf(adjS[4*r+k], mb[k], s);
            v[r] = s;
            h = fmaf(mb[r], s, h);
        }
        float nrs2 = -2.0f * rs;
#pragma unroll
        for (int r = 0; r < 4; r++) {
            float s = 0.f;
#pragma unroll
            for (int k = 0; k < 4; k++) s = fmaf(ob[4*k+r], v[k], s);
            fp[r] = s * nrs2;
        }
        float hcb = fmaf(h, rs, cb - 4.0f);

        float4* d = (float4*)&sbuf[(m * GH_TILE + g) * SB_STRIDE];
        d[0] = make_float4(Ed[0], Ed[1], Ed[2], Ed[3]);
        d[1] = make_float4(Eo[0], Eo[1], Eo[2], Eo[3]);
        d[2] = make_float4(Eo[4], Eo[5], fp[0], fp[1]);
        d[3] = make_float4(fp[2], fp[3], hcb, 0.f);
    }
    __syncthreads();

    // ---- phase 2: two n per thread ----
    int lg = tid & 15;
    int wn = tid >> 4;          // 0..7
    int gh = gh0 + lg;
    int n1 = n0 + wn;
    int n2 = n1 + 8;
    int t1 = n1 * GH + gh;
    int t2 = n2 * GH + gh;

    APack A1, A2;
    compute_apack(mu_a, sigma_a, omega_a, t1, A1);
    compute_apack(mu_a, sigma_a, omega_a, t2, A2);
    float ch1 = 0.5f * chi[t1];
    float ch2 = 0.5f * chi[t2];

    float* out1 = out + (size_t)n1 * (MM * GH) + gh;
    float* out2 = out + (size_t)n2 * (MM * GH) + gh;
    const float* sbb = &sbuf[lg * SB_STRIDE];

#pragma unroll
    for (int m = 0; m < MM; m++) {
        const float4* s4 = (const float4*)(sbb + m * (GH_TILE * SB_STRIDE));
        float4 e0 = s4[0];
        float4 e1 = s4[1];
        float4 e2 = s4[2];
        float4 e3 = s4[3];

        // split accumulators to halve the dependency chain
        float Xa1 = e3.z + A1.nca;
        float Xb1 = 0.f;
        float Xa2 = e3.z + A2.nca;
        float Xb2 = 0.f;
        Xa1 = fmaf(e0.x, A1.Cd[0], Xa1);  Xa2 = fmaf(e0.x, A2.Cd[0], Xa2);
        Xb1 = fmaf(e0.y, A1.Cd[1], Xb1);  Xb2 = fmaf(e0.y, A2.Cd[1], Xb2);
        Xa1 = fmaf(e0.z, A1.Cd[2], Xa1);  Xa2 = fmaf(e0.z, A2.Cd[2], Xa2);
        Xb1 = fmaf(e0.w, A1.Cd[3], Xb1);  Xb2 = fmaf(e0.w, A2.Cd[3], Xb2);
        Xa1 = fmaf(e1.x, A1.Co[0], Xa1);  Xa2 = fmaf(e1.x, A2.Co[0], Xa2);
        Xb1 = fmaf(e1.y, A1.Co[1], Xb1);  Xb2 = fmaf(e1.y, A2.Co[1], Xb2);
        Xa1 = fmaf(e1.z, A1.Co[2], Xa1);  Xa2 = fmaf(e1.z, A2.Co[2], Xa2);
        Xb1 = fmaf(e1.w, A1.Co[3], Xb1);  Xb2 = fmaf(e1.w, A2.Co[3], Xb2);
        Xa1 = fmaf(e2.x, A1.Co[4], Xa1);  Xa2 = fmaf(e2.x, A2.Co[4], Xa2);
        Xb1 = fmaf(e2.y, A1.Co[5], Xb1);  Xb2 = fmaf(e2.y, A2.Co[5], Xb2);
        Xa1 = fmaf(e2.z, A1.p[0], Xa1);   Xa2 = fmaf(e2.z, A2.p[0], Xa2);
        Xb1 = fmaf(e2.w, A1.p[1], Xb1);   Xb2 = fmaf(e2.w, A2.p[1], Xb2);
        Xa1 = fmaf(e3.x, A1.p[2], Xa1);   Xa2 = fmaf(e3.x, A2.p[2], Xa2);
        Xb1 = fmaf(e3.y, A1.p[3], Xb1);   Xb2 = fmaf(e3.y, A2.p[3], Xb2);

        float X1 = Xa1 + Xb1;
        float X2 = Xa2 + Xb2;

        // S = chi * sigmoid(-0.1 X) = 0.5 chi + 0.5 chi * tanh(-0.05 X)
        float th1 = fast_tanh(-0.05f * X1);
        float th2 = fast_tanh(-0.05f * X2);
        float S1 = fmaf(ch1, th1, ch1);
        float S2 = fmaf(ch2, th2, ch2);
        out1[(size_t)m * GH] = S1;
        out2[(size_t)m * GH] = S2;
    }
}

// ---------------------------------------------------------------------------
extern "C" void kernel_launch(void* const* d_in, const int* in_sizes, int n_in,
                              void* d_out, int out_size)
{
    const float* mu_a    = (const float*)d_in[0];
    const float* sigma_a = (const float*)d_in[1];
    const float* omega_a = (const float*)d_in[2];
    const float* mu_b    = (const float*)d_in[3];
    const float* sigma_b = (const float*)d_in[4];
    const float* omega_b = (const float*)d_in[5];
    const float* chi     = (const float*)d_in[6];
    float* out = (float*)d_out;

    dim3 grid(GH / GH_TILE, NN / N_TILE);   // (256, 4) = 1024 blocks
    species_fused_kernel<<<grid, NTHREADS>>>(mu_a, sigma_a, omega_a,
                                             mu_b, sigma_b, omega_b, chi, out);
}